// round 14
// baseline (speedup 1.0000x reference)
#include <cuda_runtime.h>
#include <math.h>
#include <stdint.h>

#define NM 1024
#define NM2 (NM * NM)
#define NTILE 16          // 16x16 grid of 64x64 tiles
#define NBLK 136          // upper-triangular tile count (16*17/2)
#define NTHR 256
#define NS_STEPS 7        // 4 fast-growth + 3 exact Newton-Schulz quintic
#define NS_FAST 4
#define NCHAIN 3          // normalized squarings for the spectral bound
#define PRESCALE 1.15f    // safe: fast quintic invariant on [0, 1.21]
#define ADMM_ITERS 50

// ---- static device state ----
__device__ float g_W[NM2], g_Z[NM2], g_U[NM2], g_A[NM2];
__device__ float g_Y0[NM2], g_Y1[NM2], g_T2[NM2], g_T3[NM2];
__device__ float g_part[NBLK];
__device__ unsigned int g_barcnt;

__global__ void reset_k() { g_barcnt = 0u; }

struct SM {
    float As[2][16][68];
    float Bs[2][16][64];
    float red[8];
};

// ---- packed fp32x2 helpers (sm_100-family PTX; 2 FMAs per instruction) ----
__device__ __forceinline__ uint64_t pk2(float x, float y) {
    uint64_t r;
    asm("mov.b64 %0, {%1, %2};" : "=l"(r) : "f"(x), "f"(y));
    return r;
}
__device__ __forceinline__ float2 up2(uint64_t v) {
    float2 r;
    asm("mov.b64 {%0, %1}, %2;" : "=f"(r.x), "=f"(r.y) : "l"(v));
    return r;
}
#define FMA2(acc, a, b) \
    asm("fma.rn.f32x2 %0, %1, %2, %0;" : "+l"(acc) : "l"(a), "l"(b))

// ---- grid barrier (136 CTAs, all co-resident: 1/SM on 148 SMs) ----
__device__ __forceinline__ void gridbar(unsigned int& target)
{
    __syncthreads();
    if (threadIdx.x == 0) {
        __threadfence();
        atomicAdd(&g_barcnt, 1u);
        target += NBLK;
        while (*((volatile unsigned int*)&g_barcnt) < target) { }
        __threadfence();
    }
    __syncthreads();
}

__device__ __forceinline__ void bred(SM* sm, float v)
{
#pragma unroll
    for (int o = 16; o > 0; o >>= 1) v += __shfl_down_sync(0xffffffffu, v, o);
    if ((threadIdx.x & 31) == 0) sm->red[threadIdx.x >> 5] = v;
    __syncthreads();
    if (threadIdx.x == 0) {
        float t = 0.0f;
#pragma unroll
        for (int i = 0; i < 8; ++i) t += sm->red[i];
        g_part[blockIdx.x] = t;
    }
    __syncthreads();
}

__device__ __forceinline__ float sum_parts()
{
    float s = 0.0f;
#pragma unroll 8
    for (int i = 0; i < NBLK; ++i) s += g_part[i];
    return s;
}

// ---- fp32 64x64x1024 tile GEMM, FFMA2 inner loop + symmetric mirror ----
// mode 0: plain; 1: + ||C||^2 partial (x2 off-diag); 2: fused ADMM Z/U update.
__device__ __forceinline__ void gemm_tile(SM* sm, int bm, int bn, int diag,
    const float* __restrict__ A, const float* __restrict__ B,
    float* __restrict__ C, float alpha,
    const float* __restrict__ D, float beta, int mode)
{
    const int tid = threadIdx.x;
    const int arow = tid >> 2;
    const int acol = (tid & 3) << 2;
    const int brow = tid >> 4;
    const int bcol = (tid & 15) << 2;

    const float* Ap = A + (bm + arow) * NM + acol;
    const float* Bp = B + brow * NM + bn + bcol;

    float4 a4 = *(const float4*)Ap;
    float4 b4 = *(const float4*)Bp;
    sm->As[0][acol + 0][arow] = a4.x;
    sm->As[0][acol + 1][arow] = a4.y;
    sm->As[0][acol + 2][arow] = a4.z;
    sm->As[0][acol + 3][arow] = a4.w;
    *(float4*)(&sm->Bs[0][brow][bcol]) = b4;
    __syncthreads();

    const int ty = (tid >> 4) << 2;
    const int tx = (tid & 15) << 2;

    // packed accumulators: acc01[j] = (C[ty+0][tx+j], C[ty+1][tx+j])
    //                      acc23[j] = (C[ty+2][tx+j], C[ty+3][tx+j])
    uint64_t acc01[4], acc23[4];
    const uint64_t z2 = pk2(0.0f, 0.0f);
#pragma unroll
    for (int j = 0; j < 4; ++j) { acc01[j] = z2; acc23[j] = z2; }

#pragma unroll 1
    for (int kt = 1; kt <= 64; ++kt) {
        const int cur = (kt - 1) & 1;
        if (kt < 64) {
            a4 = *(const float4*)(Ap + (kt << 4));
            b4 = *(const float4*)(Bp + (kt << 4) * NM);
        }
#pragma unroll
        for (int k = 0; k < 16; ++k) {
            const float4 av = *(const float4*)(&sm->As[cur][k][ty]);
            const float4 bv = *(const float4*)(&sm->Bs[cur][k][tx]);
            const uint64_t a01 = pk2(av.x, av.y);
            const uint64_t a23 = pk2(av.z, av.w);
            const uint64_t bd0 = pk2(bv.x, bv.x);
            const uint64_t bd1 = pk2(bv.y, bv.y);
            const uint64_t bd2 = pk2(bv.z, bv.z);
            const uint64_t bd3 = pk2(bv.w, bv.w);
            FMA2(acc01[0], a01, bd0); FMA2(acc01[1], a01, bd1);
            FMA2(acc01[2], a01, bd2); FMA2(acc01[3], a01, bd3);
            FMA2(acc23[0], a23, bd0); FMA2(acc23[1], a23, bd1);
            FMA2(acc23[2], a23, bd2); FMA2(acc23[3], a23, bd3);
        }
        if (kt < 64) {
            const int nxt = kt & 1;
            sm->As[nxt][acol + 0][arow] = a4.x;
            sm->As[nxt][acol + 1][arow] = a4.y;
            sm->As[nxt][acol + 2][arow] = a4.z;
            sm->As[nxt][acol + 3][arow] = a4.w;
            *(float4*)(&sm->Bs[nxt][brow][bcol]) = b4;
        }
        __syncthreads();
    }

    // unpack to the scalar accumulator layout used by the proven epilogue
    float acc[4][4];
#pragma unroll
    for (int j = 0; j < 4; ++j) {
        const float2 r01 = up2(acc01[j]);
        const float2 r23 = up2(acc23[j]);
        acc[0][j] = r01.x; acc[1][j] = r01.y;
        acc[2][j] = r23.x; acc[3][j] = r23.y;
    }

    float lsum = 0.0f;
    const int c0 = bn + tx;
#pragma unroll
    for (int i = 0; i < 4; ++i) {
        const int row = bm + ty + i;
        float4 v;
        v.x = acc[i][0] * alpha; v.y = acc[i][1] * alpha;
        v.z = acc[i][2] * alpha; v.w = acc[i][3] * alpha;
        if (D) {
            const float4 d = *(const float4*)(D + row * NM + c0);
            v.x += beta * d.x; v.y += beta * d.y;
            v.z += beta * d.z; v.w += beta * d.w;
        }
        if (mode == 2) {
            float vv[4] = { v.x, v.y, v.z, v.w };
#pragma unroll
            for (int j = 0; j < 4; ++j) {
                const int col = c0 + j;
                const float u_ = g_U[row * NM + col];
                float z = fmaxf(vv[j] + u_, 0.0f);
                if (row == col) z = 1.0f;
                const float un = u_ + vv[j] - z;
                g_Z[row * NM + col] = z;
                g_U[row * NM + col] = un;
                if (!diag) {
                    g_Z[col * NM + row] = z;
                    g_U[col * NM + row] = un;
                }
            }
        } else {
            *(float4*)(C + row * NM + c0) = v;
            if (!diag) {
                C[(c0 + 0) * NM + row] = v.x;
                C[(c0 + 1) * NM + row] = v.y;
                C[(c0 + 2) * NM + row] = v.z;
                C[(c0 + 3) * NM + row] = v.w;
            }
            lsum += v.x * v.x + v.y * v.y + v.z * v.z + v.w * v.w;
        }
    }
    if (mode == 1) bred(sm, diag ? lsum : 2.0f * lsum);
}

// ---- the whole ADMM solve, one persistent kernel ----
__global__ void __launch_bounds__(NTHR, 1)
sdp_k(const float* __restrict__ Win, float* __restrict__ out, int n)
{
    __shared__ SM sm;
    const int tid = threadIdx.x;
    unsigned int bt = 0;

    // decode upper-triangular tile (tm, tn)
    int u = blockIdx.x, tm = 0;
    while (u >= NTILE - tm) { u -= NTILE - tm; ++tm; }
    const int tn = tm + u;
    const int bm = tm << 6, bn = tn << 6;
    const int diag = (tm == tn);

    // init: W = sym(Win), Z = I, U = 0
    for (int e = blockIdx.x * NTHR + tid; e < NM2; e += NBLK * NTHR) {
        int i = e >> 10, j = e & 1023;
        g_W[e] = 0.5f * (Win[e] + Win[(j << 10) + i]);
        g_Z[e] = (i == j) ? 1.0f : 0.0f;
        g_U[e] = 0.0f;
    }
    gridbar(bt);

    for (int it = 0; it < ADMM_ITERS; ++it) {
        // A = sym(Z - U) + W ; ||A||_F^2
        float ls = 0.0f;
        for (int e = blockIdx.x * NTHR + tid; e < NM2; e += NBLK * NTHR) {
            int i = e >> 10, j = e & 1023;
            int et = (j << 10) + i;
            float v = 0.5f * ((g_Z[e] - g_U[e]) + (g_Z[et] - g_U[et])) + g_W[e];
            g_A[e] = v;
            ls += v * v;
        }
        bred(&sm, ls);
        gridbar(bt);

        float q[NCHAIN + 1];
        q[0] = fmaxf(sum_parts(), 1e-30f);

        // guaranteed spectral bound: 3 normalized squarings
        const float* P = g_A;
        float* Pn = g_T2;
#pragma unroll 1
        for (int k = 0; k < NCHAIN; ++k) {
            gemm_tile(&sm, bm, bn, diag, P, P, Pn, 1.0f / q[k], nullptr, 0.0f, 1);
            gridbar(bt);
            q[k + 1] = fmaxf(sum_parts(), 1e-30f);
            P = Pn;
            Pn = (Pn == g_T2) ? g_T3 : g_T2;
        }
        float ls2 = 0.5f    * log2f(q[0]) + 0.25f   * log2f(q[1])
                  + 0.125f  * log2f(q[2]) + 0.0625f * log2f(q[3]);
        const float invs = exp2f(-ls2) * PRESCALE;  // eigenvalues in [0, 1.15] < 1.21

        // Y0 = A / s (separate sweep keeps the sign loop branch-free)
        for (int e = blockIdx.x * NTHR + tid; e < NM2; e += NBLK * NTHR)
            g_Y0[e] = g_A[e] * invs;
        gridbar(bt);

        // sign iteration: 4 fast-growth + 3 exact NS quintic steps.
        float* Y = g_Y0;
        float* Yn = g_Y1;
#pragma unroll 1
        for (int s = 0; s < NS_STEPS; ++s) {
            const int fast = (s < NS_FAST);
            const float ca = fast ? 3.4445f : 1.875f;
            const float cb = fast ? -4.7750f : -1.25f;
            const float cc = fast ? 2.0315f : 0.375f;
            gemm_tile(&sm, bm, bn, diag, Y, Y, g_T2, 1.0f, nullptr, 0.0f, 0);
            gridbar(bt);
            gemm_tile(&sm, bm, bn, diag, g_T2, g_T2, g_T3, cc, g_T2, cb, 0);
            gridbar(bt);
            gemm_tile(&sm, bm, bn, diag, Y, g_T3, Yn, 1.0f, Y, ca, 0);
            gridbar(bt);
            float* tmp = Y; Y = Yn; Yn = tmp;
        }

        // X = 0.5 (A sign(A) + A), fused Z/U update (tile + mirror)
        gemm_tile(&sm, bm, bn, diag, g_A, Y, nullptr, 0.5f, g_A, 0.5f, 2);
        gridbar(bt);
    }

    // copy out top-left n x n of Z
    const int tot = n * n;
    for (int idx = blockIdx.x * NTHR + tid; idx < tot; idx += NBLK * NTHR) {
        int i = idx / n, j = idx - i * n;
        out[idx] = g_Z[i * NM + j];
    }
}

extern "C" void kernel_launch(void* const* d_in, const int* in_sizes, int n_in,
                              void* d_out, int out_size)
{
    const float* Win = (const float*)d_in[0];
    float* out = (float*)d_out;
    int n = (int)(sqrt((double)out_size) + 0.5);

    reset_k<<<1, 1>>>();
    sdp_k<<<NBLK, NTHR>>>(Win, out, n);
}

// round 15
// speedup vs baseline: 1.0531x; 1.0531x over previous
#include <cuda_runtime.h>
#include <math.h>
#include <stdint.h>

#define NM 1024
#define NM2 (NM * NM)
#define NTILE 16          // 16x16 grid of 64x64 tiles
#define NBLK 136          // upper-triangular tile count (16*17/2)
#define NTHR 256
#define NS_STEPS 7        // 4 fast-growth + 3 exact Newton-Schulz quintic
#define NS_FAST 4
#define NCHAIN 3          // normalized squarings for the spectral bound
#define PRESCALE 1.15f    // safe: fast quintic invariant on [0, 1.21]
#define ADMM_ITERS 50

// ---- static device state ----
__device__ float g_W[NM2], g_Z[NM2], g_U[NM2], g_A[NM2];
__device__ float g_Y0[NM2], g_Y1[NM2], g_T2[NM2], g_T3[NM2];
__device__ float g_part[NBLK];
__device__ unsigned int g_barcnt;

__global__ void reset_k() { g_barcnt = 0u; }

struct SM {
    float As[2][16][68];
    float Bs[2][16][64];
    float red[8];
};

// ---- grid barrier (136 CTAs, all co-resident: 1/SM on 148 SMs) ----
__device__ __forceinline__ void gridbar(unsigned int& target)
{
    __syncthreads();
    if (threadIdx.x == 0) {
        __threadfence();
        atomicAdd(&g_barcnt, 1u);
        target += NBLK;
        while (*((volatile unsigned int*)&g_barcnt) < target) { }
        __threadfence();
    }
    __syncthreads();
}

__device__ __forceinline__ void bred(SM* sm, float v)
{
#pragma unroll
    for (int o = 16; o > 0; o >>= 1) v += __shfl_down_sync(0xffffffffu, v, o);
    if ((threadIdx.x & 31) == 0) sm->red[threadIdx.x >> 5] = v;
    __syncthreads();
    if (threadIdx.x == 0) {
        float t = 0.0f;
#pragma unroll
        for (int i = 0; i < 8; ++i) t += sm->red[i];
        g_part[blockIdx.x] = t;
    }
    __syncthreads();
}

__device__ __forceinline__ float sum_parts()
{
    float s = 0.0f;
#pragma unroll 8
    for (int i = 0; i < NBLK; ++i) s += g_part[i];
    return s;
}

// ---- fp32 64x64x1024 tile GEMM (R13-proven core, INLINE, 5 call sites) ----
// mode 0: plain; 1: + ||C||^2 partial (x2 off-diag); 2: fused ADMM Z/U update.
__device__ __forceinline__ void gemm_tile(SM* sm, int bm, int bn, int diag,
    const float* __restrict__ A, const float* __restrict__ B,
    float* __restrict__ C, float alpha,
    const float* __restrict__ D, float beta, int mode)
{
    const int tid = threadIdx.x;
    const int arow = tid >> 2;
    const int acol = (tid & 3) << 2;
    const int brow = tid >> 4;
    const int bcol = (tid & 15) << 2;

    const float* Ap = A + (bm + arow) * NM + acol;
    const float* Bp = B + brow * NM + bn + bcol;

    float4 a4 = *(const float4*)Ap;
    float4 b4 = *(const float4*)Bp;
    sm->As[0][acol + 0][arow] = a4.x;
    sm->As[0][acol + 1][arow] = a4.y;
    sm->As[0][acol + 2][arow] = a4.z;
    sm->As[0][acol + 3][arow] = a4.w;
    *(float4*)(&sm->Bs[0][brow][bcol]) = b4;
    __syncthreads();

    const int ty = (tid >> 4) << 2;
    const int tx = (tid & 15) << 2;

    float acc[4][4];
#pragma unroll
    for (int i = 0; i < 4; ++i)
#pragma unroll
        for (int j = 0; j < 4; ++j) acc[i][j] = 0.0f;

#pragma unroll 1
    for (int kt = 1; kt <= 64; ++kt) {
        const int cur = (kt - 1) & 1;
        if (kt < 64) {
            a4 = *(const float4*)(Ap + (kt << 4));
            b4 = *(const float4*)(Bp + (kt << 4) * NM);
        }
#pragma unroll
        for (int k = 0; k < 16; ++k) {
            const float4 av = *(const float4*)(&sm->As[cur][k][ty]);
            const float4 bv = *(const float4*)(&sm->Bs[cur][k][tx]);
            acc[0][0] += av.x * bv.x; acc[0][1] += av.x * bv.y;
            acc[0][2] += av.x * bv.z; acc[0][3] += av.x * bv.w;
            acc[1][0] += av.y * bv.x; acc[1][1] += av.y * bv.y;
            acc[1][2] += av.y * bv.z; acc[1][3] += av.y * bv.w;
            acc[2][0] += av.z * bv.x; acc[2][1] += av.z * bv.y;
            acc[2][2] += av.z * bv.z; acc[2][3] += av.z * bv.w;
            acc[3][0] += av.w * bv.x; acc[3][1] += av.w * bv.y;
            acc[3][2] += av.w * bv.z; acc[3][3] += av.w * bv.w;
        }
        if (kt < 64) {
            const int nxt = kt & 1;
            sm->As[nxt][acol + 0][arow] = a4.x;
            sm->As[nxt][acol + 1][arow] = a4.y;
            sm->As[nxt][acol + 2][arow] = a4.z;
            sm->As[nxt][acol + 3][arow] = a4.w;
            *(float4*)(&sm->Bs[nxt][brow][bcol]) = b4;
        }
        __syncthreads();
    }

    float lsum = 0.0f;
    const int c0 = bn + tx;
#pragma unroll
    for (int i = 0; i < 4; ++i) {
        const int row = bm + ty + i;
        float4 v;
        v.x = acc[i][0] * alpha; v.y = acc[i][1] * alpha;
        v.z = acc[i][2] * alpha; v.w = acc[i][3] * alpha;
        if (D) {
            const float4 d = *(const float4*)(D + row * NM + c0);
            v.x += beta * d.x; v.y += beta * d.y;
            v.z += beta * d.z; v.w += beta * d.w;
        }
        if (mode == 2) {
            float vv[4] = { v.x, v.y, v.z, v.w };
#pragma unroll
            for (int j = 0; j < 4; ++j) {
                const int col = c0 + j;
                const float u_ = g_U[row * NM + col];
                float z = fmaxf(vv[j] + u_, 0.0f);
                if (row == col) z = 1.0f;
                const float un = u_ + vv[j] - z;
                g_Z[row * NM + col] = z;
                g_U[row * NM + col] = un;
                if (!diag) {
                    g_Z[col * NM + row] = z;
                    g_U[col * NM + row] = un;
                }
            }
        } else {
            *(float4*)(C + row * NM + c0) = v;
            if (!diag) {
                C[(c0 + 0) * NM + row] = v.x;
                C[(c0 + 1) * NM + row] = v.y;
                C[(c0 + 2) * NM + row] = v.z;
                C[(c0 + 3) * NM + row] = v.w;
            }
            lsum += v.x * v.x + v.y * v.y + v.z * v.z + v.w * v.w;
        }
    }
    if (mode == 1) bred(sm, diag ? lsum : 2.0f * lsum);
}

// ---- the whole ADMM solve, one persistent kernel ----
__global__ void __launch_bounds__(NTHR, 1)
sdp_k(const float* __restrict__ Win, float* __restrict__ out, int n)
{
    __shared__ SM sm;
    const int tid = threadIdx.x;
    unsigned int bt = 0;

    // decode upper-triangular tile (tm, tn)
    int u = blockIdx.x, tm = 0;
    while (u >= NTILE - tm) { u -= NTILE - tm; ++tm; }
    const int tn = tm + u;
    const int bm = tm << 6, bn = tn << 6;
    const int diag = (tm == tn);

    // init: W = sym(Win), Z = I, U = 0
    for (int e = blockIdx.x * NTHR + tid; e < NM2; e += NBLK * NTHR) {
        int i = e >> 10, j = e & 1023;
        g_W[e] = 0.5f * (Win[e] + Win[(j << 10) + i]);
        g_Z[e] = (i == j) ? 1.0f : 0.0f;
        g_U[e] = 0.0f;
    }
    gridbar(bt);

    for (int it = 0; it < ADMM_ITERS; ++it) {
        // A = sym(Z - U) + W ; ||A||_F^2
        float ls = 0.0f;
        for (int e = blockIdx.x * NTHR + tid; e < NM2; e += NBLK * NTHR) {
            int i = e >> 10, j = e & 1023;
            int et = (j << 10) + i;
            float v = 0.5f * ((g_Z[e] - g_U[e]) + (g_Z[et] - g_U[et])) + g_W[e];
            g_A[e] = v;
            ls += v * v;
        }
        bred(&sm, ls);
        gridbar(bt);

        float q[NCHAIN + 1];
        q[0] = fmaxf(sum_parts(), 1e-30f);

        // guaranteed spectral bound: 3 normalized squarings.
        // Buffer plan PRESERVES T2 = A^2/q0 for reuse in sign step 0:
        //   k0: T2 = A^2/q0 ; k1: T3 = T2^2/q1 ; k2: Y1 = T3^2/q2
        {
            const float* Pin[NCHAIN]  = { g_A, g_T2, g_T3 };
            float*       Pout[NCHAIN] = { g_T2, g_T3, g_Y1 };
#pragma unroll 1
            for (int k = 0; k < NCHAIN; ++k) {
                gemm_tile(&sm, bm, bn, diag, Pin[k], Pin[k], Pout[k],
                          1.0f / q[k], nullptr, 0.0f, 1);
                gridbar(bt);
                q[k + 1] = fmaxf(sum_parts(), 1e-30f);
            }
        }
        float ls2 = 0.5f    * log2f(q[0]) + 0.25f   * log2f(q[1])
                  + 0.125f  * log2f(q[2]) + 0.0625f * log2f(q[3]);
        const float invs = exp2f(-ls2) * PRESCALE;  // eigenvalues in [0, 1.15] < 1.21

        // sign iteration: 4 fast-growth + 3 exact NS quintic steps.
        // Step 0 reuses the chain's T2 = A^2/q0:  Y0^2 = (invs^2*q0)*T2,
        // so its squaring GEMM and the Y0 sweep are both eliminated.
        float* Y = g_Y1;   // not read at s=0
        float* Yn = g_Y0;
#pragma unroll 1
        for (int s = 0; s < NS_STEPS; ++s) {
            const int fast = (s < NS_FAST);
            const float ca = fast ? 3.4445f : 1.875f;
            const float cb = fast ? -4.7750f : -1.25f;
            const float cc = fast ? 2.0315f : 0.375f;

            float g2a, g2b, g3al, g3be;
            const float* Ysrc;
            if (s == 0) {
                const float c = invs * invs * q[0];  // Y0^2 = c * T2
                g2a = cc * c * c; g2b = cb * c;
                g3al = invs;      g3be = ca * invs;
                Ysrc = g_A;
            } else {
                g2a = cc; g2b = cb;
                g3al = 1.0f; g3be = ca;
                Ysrc = Y;
                gemm_tile(&sm, bm, bn, diag, Y, Y, g_T2, 1.0f, nullptr, 0.0f, 0);
                gridbar(bt);
            }
            gemm_tile(&sm, bm, bn, diag, g_T2, g_T2, g_T3, g2a, g_T2, g2b, 0);
            gridbar(bt);
            gemm_tile(&sm, bm, bn, diag, Ysrc, g_T3, Yn, g3al, Ysrc, g3be, 0);
            gridbar(bt);
            float* tmp = Y; Y = Yn; Yn = tmp;
        }

        // X = 0.5 (A sign(A) + A), fused Z/U update (tile + mirror)
        gemm_tile(&sm, bm, bn, diag, g_A, Y, nullptr, 0.5f, g_A, 0.5f, 2);
        gridbar(bt);
    }

    // copy out top-left n x n of Z
    const int tot = n * n;
    for (int idx = blockIdx.x * NTHR + tid; idx < tot; idx += NBLK * NTHR) {
        int i = idx / n, j = idx - i * n;
        out[idx] = g_Z[i * NM + j];
    }
}

extern "C" void kernel_launch(void* const* d_in, const int* in_sizes, int n_in,
                              void* d_out, int out_size)
{
    const float* Win = (const float*)d_in[0];
    float* out = (float*)d_out;
    int n = (int)(sqrt((double)out_size) + 0.5);

    reset_k<<<1, 1>>>();
    sdp_k<<<NBLK, NTHR>>>(Win, out, n);
}

// round 16
// speedup vs baseline: 1.1039x; 1.0482x over previous
#include <cuda_runtime.h>
#include <math.h>
#include <stdint.h>

#define NM 1024
#define NM2 (NM * NM)
#define NTILE 16          // 16x16 grid of 64x64 tiles
#define NBLK 136          // upper-triangular tile count (16*17/2)
#define NTHR 256
#define NS_STEPS 7        // 4 fast-growth + 3 exact Newton-Schulz quintic
#define NS_FAST 4
#define NCHAIN 2          // normalized squarings for the spectral bound
#define PRESCALE 1.15f    // safe: fast quintic invariant on [0, 1.21]
#define ADMM_ITERS 50

// ---- static device state ----
__device__ float g_W[NM2], g_Z[NM2], g_U[NM2], g_A[NM2];
__device__ float g_Y0[NM2], g_Y1[NM2], g_T2[NM2], g_T3[NM2];
__device__ float g_part[NBLK];
__device__ unsigned int g_barcnt;

__global__ void reset_k() { g_barcnt = 0u; }

struct SM {
    float As[2][16][68];
    float Bs[2][16][64];
    float red[8];
};

// ---- grid barrier (136 CTAs, all co-resident: 1/SM on 148 SMs) ----
__device__ __forceinline__ void gridbar(unsigned int& target)
{
    __syncthreads();
    if (threadIdx.x == 0) {
        __threadfence();
        atomicAdd(&g_barcnt, 1u);
        target += NBLK;
        while (*((volatile unsigned int*)&g_barcnt) < target) { }
        __threadfence();
    }
    __syncthreads();
}

__device__ __forceinline__ void bred(SM* sm, float v)
{
#pragma unroll
    for (int o = 16; o > 0; o >>= 1) v += __shfl_down_sync(0xffffffffu, v, o);
    if ((threadIdx.x & 31) == 0) sm->red[threadIdx.x >> 5] = v;
    __syncthreads();
    if (threadIdx.x == 0) {
        float t = 0.0f;
#pragma unroll
        for (int i = 0; i < 8; ++i) t += sm->red[i];
        g_part[blockIdx.x] = t;
    }
    __syncthreads();
}

__device__ __forceinline__ float sum_parts()
{
    float s = 0.0f;
#pragma unroll 8
    for (int i = 0; i < NBLK; ++i) s += g_part[i];
    return s;
}

// ---- fp32 64x64x1024 tile GEMM (proven core, INLINE, 5 call sites) ----
// mode 0: plain; 1: + ||C||^2 partial (x2 off-diag); 2: fused ADMM Z/U update.
__device__ __forceinline__ void gemm_tile(SM* sm, int bm, int bn, int diag,
    const float* __restrict__ A, const float* __restrict__ B,
    float* __restrict__ C, float alpha,
    const float* __restrict__ D, float beta, int mode)
{
    const int tid = threadIdx.x;
    const int arow = tid >> 2;
    const int acol = (tid & 3) << 2;
    const int brow = tid >> 4;
    const int bcol = (tid & 15) << 2;

    const float* Ap = A + (bm + arow) * NM + acol;
    const float* Bp = B + brow * NM + bn + bcol;

    float4 a4 = *(const float4*)Ap;
    float4 b4 = *(const float4*)Bp;
    sm->As[0][acol + 0][arow] = a4.x;
    sm->As[0][acol + 1][arow] = a4.y;
    sm->As[0][acol + 2][arow] = a4.z;
    sm->As[0][acol + 3][arow] = a4.w;
    *(float4*)(&sm->Bs[0][brow][bcol]) = b4;
    __syncthreads();

    const int ty = (tid >> 4) << 2;
    const int tx = (tid & 15) << 2;

    float acc[4][4];
#pragma unroll
    for (int i = 0; i < 4; ++i)
#pragma unroll
        for (int j = 0; j < 4; ++j) acc[i][j] = 0.0f;

#pragma unroll 1
    for (int kt = 1; kt <= 64; ++kt) {
        const int cur = (kt - 1) & 1;
        if (kt < 64) {
            a4 = *(const float4*)(Ap + (kt << 4));
            b4 = *(const float4*)(Bp + (kt << 4) * NM);
        }
#pragma unroll
        for (int k = 0; k < 16; ++k) {
            const float4 av = *(const float4*)(&sm->As[cur][k][ty]);
            const float4 bv = *(const float4*)(&sm->Bs[cur][k][tx]);
            acc[0][0] += av.x * bv.x; acc[0][1] += av.x * bv.y;
            acc[0][2] += av.x * bv.z; acc[0][3] += av.x * bv.w;
            acc[1][0] += av.y * bv.x; acc[1][1] += av.y * bv.y;
            acc[1][2] += av.y * bv.z; acc[1][3] += av.y * bv.w;
            acc[2][0] += av.z * bv.x; acc[2][1] += av.z * bv.y;
            acc[2][2] += av.z * bv.z; acc[2][3] += av.z * bv.w;
            acc[3][0] += av.w * bv.x; acc[3][1] += av.w * bv.y;
            acc[3][2] += av.w * bv.z; acc[3][3] += av.w * bv.w;
        }
        if (kt < 64) {
            const int nxt = kt & 1;
            sm->As[nxt][acol + 0][arow] = a4.x;
            sm->As[nxt][acol + 1][arow] = a4.y;
            sm->As[nxt][acol + 2][arow] = a4.z;
            sm->As[nxt][acol + 3][arow] = a4.w;
            *(float4*)(&sm->Bs[nxt][brow][bcol]) = b4;
        }
        __syncthreads();
    }

    float lsum = 0.0f;
    const int c0 = bn + tx;
#pragma unroll
    for (int i = 0; i < 4; ++i) {
        const int row = bm + ty + i;
        float4 v;
        v.x = acc[i][0] * alpha; v.y = acc[i][1] * alpha;
        v.z = acc[i][2] * alpha; v.w = acc[i][3] * alpha;
        if (D) {
            const float4 d = *(const float4*)(D + row * NM + c0);
            v.x += beta * d.x; v.y += beta * d.y;
            v.z += beta * d.z; v.w += beta * d.w;
        }
        if (mode == 2) {
            float vv[4] = { v.x, v.y, v.z, v.w };
#pragma unroll
            for (int j = 0; j < 4; ++j) {
                const int col = c0 + j;
                const float u_ = g_U[row * NM + col];
                float z = fmaxf(vv[j] + u_, 0.0f);
                if (row == col) z = 1.0f;
                const float un = u_ + vv[j] - z;
                g_Z[row * NM + col] = z;
                g_U[row * NM + col] = un;
                if (!diag) {
                    g_Z[col * NM + row] = z;
                    g_U[col * NM + row] = un;
                }
            }
        } else {
            *(float4*)(C + row * NM + c0) = v;
            if (!diag) {
                C[(c0 + 0) * NM + row] = v.x;
                C[(c0 + 1) * NM + row] = v.y;
                C[(c0 + 2) * NM + row] = v.z;
                C[(c0 + 3) * NM + row] = v.w;
            }
            lsum += v.x * v.x + v.y * v.y + v.z * v.z + v.w * v.w;
        }
    }
    if (mode == 1) bred(sm, diag ? lsum : 2.0f * lsum);
}

// ---- the whole ADMM solve, one persistent kernel ----
__global__ void __launch_bounds__(NTHR, 1)
sdp_k(const float* __restrict__ Win, float* __restrict__ out, int n)
{
    __shared__ SM sm;
    const int tid = threadIdx.x;
    unsigned int bt = 0;

    // decode upper-triangular tile (tm, tn)
    int u = blockIdx.x, tm = 0;
    while (u >= NTILE - tm) { u -= NTILE - tm; ++tm; }
    const int tn = tm + u;
    const int bm = tm << 6, bn = tn << 6;
    const int diag = (tm == tn);

    // init: W = sym(Win), Z = I, U = 0
    for (int e = blockIdx.x * NTHR + tid; e < NM2; e += NBLK * NTHR) {
        int i = e >> 10, j = e & 1023;
        g_W[e] = 0.5f * (Win[e] + Win[(j << 10) + i]);
        g_Z[e] = (i == j) ? 1.0f : 0.0f;
        g_U[e] = 0.0f;
    }
    gridbar(bt);

    for (int it = 0; it < ADMM_ITERS; ++it) {
        // A = sym(Z - U) + W ; ||A||_F^2
        float ls = 0.0f;
        for (int e = blockIdx.x * NTHR + tid; e < NM2; e += NBLK * NTHR) {
            int i = e >> 10, j = e & 1023;
            int et = (j << 10) + i;
            float v = 0.5f * ((g_Z[e] - g_U[e]) + (g_Z[et] - g_U[et])) + g_W[e];
            g_A[e] = v;
            ls += v * v;
        }
        bred(&sm, ls);
        gridbar(bt);

        float q[NCHAIN + 1];
        q[0] = fmaxf(sum_parts(), 1e-30f);

        // guaranteed spectral bound: 2 normalized squarings.
        // lambda_max(A)^4 <= q0^2 * q1 * sqrt(q2)  =>  s = q0^1/2 q1^1/4 q2^1/8.
        // T2 = A^2/q0 is PRESERVED for reuse in sign step 0; T3 is norm-only
        // (immediately overwritten by step 0's polynomial GEMM).
        {
            const float* Pin[NCHAIN]  = { g_A, g_T2 };
            float*       Pout[NCHAIN] = { g_T2, g_T3 };
#pragma unroll 1
            for (int k = 0; k < NCHAIN; ++k) {
                gemm_tile(&sm, bm, bn, diag, Pin[k], Pin[k], Pout[k],
                          1.0f / q[k], nullptr, 0.0f, 1);
                gridbar(bt);
                q[k + 1] = fmaxf(sum_parts(), 1e-30f);
            }
        }
        float ls2 = 0.5f   * log2f(q[0]) + 0.25f * log2f(q[1])
                  + 0.125f * log2f(q[2]);
        const float invs = exp2f(-ls2) * PRESCALE;  // eigenvalues in [0, 1.15] < 1.21

        // sign iteration: 4 fast-growth + 3 exact NS quintic steps.
        // Step 0 reuses the chain's T2 = A^2/q0:  Y0^2 = (invs^2*q0)*T2,
        // so its squaring GEMM and the Y0 sweep are both eliminated.
        float* Y = g_Y1;   // not read at s=0
        float* Yn = g_Y0;
#pragma unroll 1
        for (int s = 0; s < NS_STEPS; ++s) {
            const int fast = (s < NS_FAST);
            const float ca = fast ? 3.4445f : 1.875f;
            const float cb = fast ? -4.7750f : -1.25f;
            const float cc = fast ? 2.0315f : 0.375f;

            float g2a, g2b, g3al, g3be;
            const float* Ysrc;
            if (s == 0) {
                const float c = invs * invs * q[0];  // Y0^2 = c * T2
                g2a = cc * c * c; g2b = cb * c;
                g3al = invs;      g3be = ca * invs;
                Ysrc = g_A;
            } else {
                g2a = cc; g2b = cb;
                g3al = 1.0f; g3be = ca;
                Ysrc = Y;
                gemm_tile(&sm, bm, bn, diag, Y, Y, g_T2, 1.0f, nullptr, 0.0f, 0);
                gridbar(bt);
            }
            gemm_tile(&sm, bm, bn, diag, g_T2, g_T2, g_T3, g2a, g_T2, g2b, 0);
            gridbar(bt);
            gemm_tile(&sm, bm, bn, diag, Ysrc, g_T3, Yn, g3al, Ysrc, g3be, 0);
            gridbar(bt);
            float* tmp = Y; Y = Yn; Yn = tmp;
        }

        // X = 0.5 (A sign(A) + A), fused Z/U update (tile + mirror)
        gemm_tile(&sm, bm, bn, diag, g_A, Y, nullptr, 0.5f, g_A, 0.5f, 2);
        gridbar(bt);
    }

    // copy out top-left n x n of Z
    const int tot = n * n;
    for (int idx = blockIdx.x * NTHR + tid; idx < tot; idx += NBLK * NTHR) {
        int i = idx / n, j = idx - i * n;
        out[idx] = g_Z[i * NM + j];
    }
}

extern "C" void kernel_launch(void* const* d_in, const int* in_sizes, int n_in,
                              void* d_out, int out_size)
{
    const float* Win = (const float*)d_in[0];
    float* out = (float*)d_out;
    int n = (int)(sqrt((double)out_size) + 0.5);

    reset_k<<<1, 1>>>();
    sdp_k<<<NBLK, NTHR>>>(Win, out, n);
}